// round 2
// baseline (speedup 1.0000x reference)
#include <cuda_runtime.h>
#include <mma.h>
#include <math_constants.h>
using namespace nvcuda;

// Problem shape (fixed)
static constexpr int Bb = 2, Tt = 2048, Cc = 1024, Hh = 16, Dd = 64;

// Scratch (allocation-free: device globals)
__device__ float g_qkv[(size_t)Bb * Tt * 3 * Cc];   // 50 MB
__device__ float g_y[(size_t)Bb * Tt * Cc];         // 16 MB

template <class Frag>
__device__ __forceinline__ void cvt_tf32(Frag& f) {
#pragma unroll
    for (int t = 0; t < f.num_elements; t++) f.x[t] = wmma::__float_to_tf32(f.x[t]);
}

// ---------------------------------------------------------------------------
// Projection GEMM: C[M,N] = A[M,K] @ B[N,K]^T   (row-major, lda=ldb=K, ldc=N)
// 128x128 block tile, BK=32, 256 threads, 8 warps as 4x2, warp tile 32x64.
// ---------------------------------------------------------------------------
static constexpr int GBM = 128, GBN = 128, GBK = 32;
static constexpr int GLD = GBK + 4;   // 36 floats, rows 144B (16B multiple)

__global__ void __launch_bounds__(256)
gemm_nt(const float* __restrict__ A, const float* __restrict__ B,
        float* __restrict__ C, int M, int N, int K)
{
    __shared__ float As[GBM * GLD];
    __shared__ float Bs[GBN * GLD];

    const int bm = blockIdx.y * GBM;
    const int bn = blockIdx.x * GBN;
    const int tid = threadIdx.x;
    const int warp = tid >> 5;
    const int wm = (warp >> 1) * 32;   // 4 warps along M
    const int wn = (warp & 1) * 64;    // 2 warps along N

    wmma::fragment<wmma::accumulator, 16, 16, 8, float> acc[2][4];
#pragma unroll
    for (int i = 0; i < 2; i++)
#pragma unroll
        for (int j = 0; j < 4; j++) wmma::fill_fragment(acc[i][j], 0.0f);

    for (int k0 = 0; k0 < K; k0 += GBK) {
        __syncthreads();
        // 128x32 tiles: 1024 float4, 4 per thread per matrix
#pragma unroll
        for (int it = 0; it < 4; it++) {
            int i = tid + it * 256;
            int r = i >> 3, c4 = (i & 7) * 4;
            *(float4*)&As[r * GLD + c4] =
                *(const float4*)(A + (size_t)(bm + r) * K + k0 + c4);
            *(float4*)&Bs[r * GLD + c4] =
                *(const float4*)(B + (size_t)(bn + r) * K + k0 + c4);
        }
        __syncthreads();

#pragma unroll
        for (int kk = 0; kk < GBK; kk += 8) {
            wmma::fragment<wmma::matrix_a, 16, 16, 8, wmma::precision::tf32,
                           wmma::row_major> af[2];
            wmma::fragment<wmma::matrix_b, 16, 16, 8, wmma::precision::tf32,
                           wmma::col_major> bf[4];
#pragma unroll
            for (int i = 0; i < 2; i++) {
                wmma::load_matrix_sync(af[i], &As[(wm + 16 * i) * GLD + kk], GLD);
                cvt_tf32(af[i]);
            }
#pragma unroll
            for (int j = 0; j < 4; j++) {
                wmma::load_matrix_sync(bf[j], &Bs[(wn + 16 * j) * GLD + kk], GLD);
                cvt_tf32(bf[j]);
            }
#pragma unroll
            for (int i = 0; i < 2; i++)
#pragma unroll
                for (int j = 0; j < 4; j++)
                    wmma::mma_sync(acc[i][j], af[i], bf[j], acc[i][j]);
        }
    }

#pragma unroll
    for (int i = 0; i < 2; i++)
#pragma unroll
        for (int j = 0; j < 4; j++)
            wmma::store_matrix_sync(C + (size_t)(bm + wm + 16 * i) * N + bn + wn + 16 * j,
                                    acc[i][j], N, wmma::mem_row_major);
}

// ---------------------------------------------------------------------------
// Fused flash attention. One block = (b, h, 64 query rows). 128 threads.
// Q frags in registers across the KV loop; K/V tiles + S/P + O staged in smem.
// Online softmax done via smem with a 2-threads-per-row mapping.
// ---------------------------------------------------------------------------
static constexpr int FLD = 68;                        // 64 + 4 pad
static constexpr int FTILE = 64 * FLD;                // floats per 64x64 tile
static constexpr int FSMEM_BYTES = (4 * FTILE + 128) * 4;

__global__ void __launch_bounds__(128)
flash_attn(const float* __restrict__ qkv, float* __restrict__ y)
{
    extern __shared__ float sm[];
    float* Qs  = sm;                 // doubles as S/P buffer after Q frags loaded
    float* Ks  = sm + FTILE;
    float* Vs  = sm + 2 * FTILE;
    float* Os  = sm + 3 * FTILE;
    float* m_s = sm + 4 * FTILE;
    float* l_s = m_s + 64;

    const int tid  = threadIdx.x;
    const int warp = tid >> 5;
    const int q0   = blockIdx.x * 64;
    const int b    = blockIdx.y >> 4;
    const int h    = blockIdx.y & 15;
    const float* base = qkv + (size_t)b * Tt * 3 * Cc + (size_t)h * Dd;

    // Load Q tile (pre-scaled by 1/sqrt(D)), zero O, init m/l
#pragma unroll
    for (int it = 0; it < 8; it++) {
        int i = tid + it * 128;
        int r = i >> 4, c4 = (i & 15) * 4;
        float4 v = *(const float4*)(base + (size_t)(q0 + r) * (3 * Cc) + c4);
        v.x *= 0.125f; v.y *= 0.125f; v.z *= 0.125f; v.w *= 0.125f;
        *(float4*)&Qs[r * FLD + c4] = v;
        *(float4*)&Os[r * FLD + c4] = make_float4(0.f, 0.f, 0.f, 0.f);
    }
    if (tid < 64) { m_s[tid] = -CUDART_INF_F; l_s[tid] = 0.0f; }
    __syncthreads();

    // Q fragments in registers (16 rows per warp x 64 cols = 8 k-chunks)
    wmma::fragment<wmma::matrix_a, 16, 16, 8, wmma::precision::tf32,
                   wmma::row_major> qf[8];
#pragma unroll
    for (int kk = 0; kk < 8; kk++) {
        wmma::load_matrix_sync(qf[kk], &Qs[(warp * 16) * FLD + kk * 8], FLD);
        cvt_tf32(qf[kk]);
    }

    const int row = tid >> 1;            // softmax mapping: 2 threads per row
    const int off = (tid & 1) * 32;

    for (int kv0 = 0; kv0 < Tt; kv0 += 64) {
        __syncthreads();   // prev PV done; safe to overwrite Ks/Vs and Qs(S)

        // Load K and V tiles
        const float* kb = base + Cc     + (size_t)kv0 * (3 * Cc);
        const float* vb = base + 2 * Cc + (size_t)kv0 * (3 * Cc);
#pragma unroll
        for (int it = 0; it < 8; it++) {
            int i = tid + it * 128;
            int r = i >> 4, c4 = (i & 15) * 4;
            *(float4*)&Ks[r * FLD + c4] = *(const float4*)(kb + (size_t)r * (3 * Cc) + c4);
            *(float4*)&Vs[r * FLD + c4] = *(const float4*)(vb + (size_t)r * (3 * Cc) + c4);
        }
        __syncthreads();

        // S = Q @ K^T  (each warp: 16x64)
        {
            wmma::fragment<wmma::accumulator, 16, 16, 8, float> sacc[4];
#pragma unroll
            for (int j = 0; j < 4; j++) wmma::fill_fragment(sacc[j], 0.0f);
#pragma unroll
            for (int kk = 0; kk < 8; kk++) {
#pragma unroll
                for (int j = 0; j < 4; j++) {
                    wmma::fragment<wmma::matrix_b, 16, 16, 8, wmma::precision::tf32,
                                   wmma::col_major> bf;
                    wmma::load_matrix_sync(bf, &Ks[(j * 16) * FLD + kk * 8], FLD);
                    cvt_tf32(bf);
                    wmma::mma_sync(sacc[j], qf[kk], bf, sacc[j]);
                }
            }
#pragma unroll
            for (int j = 0; j < 4; j++)
                wmma::store_matrix_sync(&Qs[(warp * 16) * FLD + j * 16], sacc[j],
                                        FLD, wmma::mem_row_major);
        }
        __syncthreads();

        // Online softmax on S rows + rescale O rows
        {
            float* srow = &Qs[row * FLD + off];
            float* orow = &Os[row * FLD + off];
            float mprev = m_s[row];
            float tmax = -CUDART_INF_F;
#pragma unroll
            for (int c = 0; c < 32; c++) tmax = fmaxf(tmax, srow[c]);
            tmax = fmaxf(tmax, __shfl_xor_sync(0xffffffffu, tmax, 1));
            float mnew = fmaxf(mprev, tmax);
            float f = __expf(mprev - mnew);
            float psum = 0.0f;
#pragma unroll
            for (int c = 0; c < 32; c++) {
                float e = __expf(srow[c] - mnew);
                srow[c] = e;
                psum += e;
                orow[c] *= f;
            }
            psum += __shfl_xor_sync(0xffffffffu, psum, 1);
            if ((tid & 1) == 0) { m_s[row] = mnew; l_s[row] = l_s[row] * f + psum; }
        }
        __syncthreads();

        // O += P @ V  (each warp: 16x64), accumulate through smem O
        {
            wmma::fragment<wmma::accumulator, 16, 16, 8, float> oacc[4];
#pragma unroll
            for (int j = 0; j < 4; j++)
                wmma::load_matrix_sync(oacc[j], &Os[(warp * 16) * FLD + j * 16],
                                       FLD, wmma::mem_row_major);
#pragma unroll
            for (int kk = 0; kk < 8; kk++) {
                wmma::fragment<wmma::matrix_a, 16, 16, 8, wmma::precision::tf32,
                               wmma::row_major> pf;
                wmma::load_matrix_sync(pf, &Qs[(warp * 16) * FLD + kk * 8], FLD);
                cvt_tf32(pf);
#pragma unroll
                for (int j = 0; j < 4; j++) {
                    wmma::fragment<wmma::matrix_b, 16, 16, 8, wmma::precision::tf32,
                                   wmma::row_major> vf;
                    wmma::load_matrix_sync(vf, &Vs[(kk * 8) * FLD + j * 16], FLD);
                    cvt_tf32(vf);
                    wmma::mma_sync(oacc[j], pf, vf, oacc[j]);
                }
            }
#pragma unroll
            for (int j = 0; j < 4; j++)
                wmma::store_matrix_sync(&Os[(warp * 16) * FLD + j * 16], oacc[j],
                                        FLD, wmma::mem_row_major);
        }
    }
    __syncthreads();

    // Epilogue: O / l  ->  y[b, q0+row, h*64 + c]
    {
        float inv = 1.0f / l_s[row];
        float* dst = y + (size_t)b * Tt * Cc + (size_t)(q0 + row) * Cc + h * Dd + off;
#pragma unroll
        for (int c = 0; c < 32; c += 4) {
            float4 v = *(float4*)&Os[row * FLD + off + c];
            v.x *= inv; v.y *= inv; v.z *= inv; v.w *= inv;
            *(float4*)(dst + c) = v;
        }
    }
}

// ---------------------------------------------------------------------------
extern "C" void kernel_launch(void* const* d_in, const int* in_sizes, int n_in,
                              void* d_out, int out_size)
{
    const float* x     = (const float*)d_in[0];
    const float* W_qkv = (const float*)d_in[3];
    const float* W_out = (const float*)d_in[4];
    float* out = (float*)d_out;

    float *qkv, *y;
    cudaGetSymbolAddress((void**)&qkv, g_qkv);
    cudaGetSymbolAddress((void**)&y, g_y);

    cudaFuncSetAttribute(flash_attn, cudaFuncAttributeMaxDynamicSharedMemorySize,
                         FSMEM_BYTES);

    // 1) qkv = x @ W_qkv^T : [4096, 3072, 1024]
    gemm_nt<<<dim3(3 * Cc / GBN, Bb * Tt / GBM), 256>>>(
        x, W_qkv, qkv, Bb * Tt, 3 * Cc, Cc);

    // 2) fused attention -> y [B, T, C]
    flash_attn<<<dim3(Tt / 64, Bb * Hh), 128, FSMEM_BYTES>>>(qkv, y);

    // 3) out = y @ W_out^T : [4096, 1024, 1024]
    gemm_nt<<<dim3(Cc / GBN, Bb * Tt / GBM), 256>>>(
        y, W_out, out, Bb * Tt, Cc, Cc);
}

// round 4
// speedup vs baseline: 2.4463x; 2.4463x over previous
#include <cuda_runtime.h>
#include <cstdint>
#include <math_constants.h>

// Problem shape (fixed)
static constexpr int Bb = 2, Tt = 2048, Cc = 1024, Hh = 16, Dd = 64;

// Scratch (allocation-free device globals)
__device__ __align__(256) float g_qkv[(size_t)Bb * Tt * 3 * Cc];   // 50 MB
__device__ __align__(256) float g_y[(size_t)Bb * Tt * Cc];         // 16 MB

// ---------------------------------------------------------------------------
// Helpers
// ---------------------------------------------------------------------------
__device__ __forceinline__ uint32_t smem_u32(const void* p) {
    uint32_t a;
    asm("{ .reg .u64 t; cvta.to.shared.u64 t, %1; cvt.u32.u64 %0, t; }"
        : "=r"(a) : "l"(p));
    return a;
}
__device__ __forceinline__ uint32_t f2tf(float x) {
    uint32_t r;
    asm("cvt.rna.tf32.f32 %0, %1;" : "=r"(r) : "f"(x));
    return r;
}
__device__ __forceinline__ void mma8(float c[4], const uint32_t a[4],
                                     const uint32_t b[2]) {
    asm volatile(
        "mma.sync.aligned.m16n8k8.row.col.f32.tf32.tf32.f32 "
        "{%0,%1,%2,%3}, {%4,%5,%6,%7}, {%8,%9}, {%0,%1,%2,%3};"
        : "+f"(c[0]), "+f"(c[1]), "+f"(c[2]), "+f"(c[3])
        : "r"(a[0]), "r"(a[1]), "r"(a[2]), "r"(a[3]), "r"(b[0]), "r"(b[1]));
}
__device__ __forceinline__ void cpa16(uint32_t dst, const void* src) {
    asm volatile("cp.async.cg.shared.global [%0], [%1], 16;"
                 :: "r"(dst), "l"(src));
}
#define CP_COMMIT() asm volatile("cp.async.commit_group;" ::: "memory")
#define CP_WAIT(n)  asm volatile("cp.async.wait_group %0;" :: "n"(n) : "memory")

// ---------------------------------------------------------------------------
// Projection GEMM: C[M,N] = A[M,K] @ B[N,K]^T (row-major, K contiguous)
// 128x128x32 tiles, 256 threads, warp tile 64x32, cp.async double buffer.
// ---------------------------------------------------------------------------
static constexpr int GLD = 36;                 // smem row stride (floats)
static constexpr int GSTG = 2 * 128 * GLD;     // floats per stage (A+B)
static constexpr int GSMEM = 2 * GSTG * 4;     // 73728 bytes

__global__ void __launch_bounds__(256, 2)
gemm_nt_mma(const float* __restrict__ A, const float* __restrict__ B,
            float* __restrict__ C, int N, int K)
{
    extern __shared__ float sm[];
    const uint32_t sb = smem_u32(sm);
    const int tid = threadIdx.x, warp = tid >> 5, lane = tid & 31;
    const int g = lane >> 2, tig = lane & 3;
    const int bm = blockIdx.y * 128, bn = blockIdx.x * 128;
    const int wm = (warp >> 2) * 64, wn = (warp & 3) * 32;

    float acc[4][4][4];
#pragma unroll
    for (int mt = 0; mt < 4; mt++)
#pragma unroll
        for (int nt = 0; nt < 4; nt++)
#pragma unroll
            for (int q = 0; q < 4; q++) acc[mt][nt][q] = 0.0f;

    auto load_stage = [&](int c, int s) {
        const float* ga = A + (size_t)bm * K + c * 32;
        const float* gb = B + (size_t)bn * K + c * 32;
        const uint32_t da = sb + (uint32_t)s * GSTG * 4;
        const uint32_t db = da + 128 * GLD * 4;
#pragma unroll
        for (int it = 0; it < 4; it++) {
            int j = tid + it * 256;           // 1024 chunks of 16B
            int r = j >> 3, ch = j & 7;
            cpa16(da + (uint32_t)(r * GLD + ch * 4) * 4,
                  ga + (size_t)r * K + ch * 4);
        }
#pragma unroll
        for (int it = 0; it < 4; it++) {
            int j = tid + it * 256;
            int r = j >> 3, ch = j & 7;
            cpa16(db + (uint32_t)(r * GLD + ch * 4) * 4,
                  gb + (size_t)r * K + ch * 4);
        }
        CP_COMMIT();
    };

    const int NCH = K / 32;
    load_stage(0, 0);
#pragma unroll 1
    for (int c = 0; c < NCH; c++) {
        CP_WAIT(0);
        __syncthreads();
        if (c + 1 < NCH) load_stage(c + 1, (c + 1) & 1);
        const float* as = sm + (c & 1) * GSTG;
        const float* bs = as + 128 * GLD;
#pragma unroll
        for (int ks = 0; ks < 4; ks++) {
            const int kc = ks * 8;
            uint32_t af[4][4], bf[4][2];
#pragma unroll
            for (int mt = 0; mt < 4; mt++) {
                const float* p = as + (wm + mt * 16 + g) * GLD + kc + tig;
                af[mt][0] = f2tf(p[0]);
                af[mt][1] = f2tf(p[8 * GLD]);
                af[mt][2] = f2tf(p[4]);
                af[mt][3] = f2tf(p[8 * GLD + 4]);
            }
#pragma unroll
            for (int nt = 0; nt < 4; nt++) {
                const float* p = bs + (wn + nt * 8 + g) * GLD + kc + tig;
                bf[nt][0] = f2tf(p[0]);
                bf[nt][1] = f2tf(p[4]);
            }
#pragma unroll
            for (int mt = 0; mt < 4; mt++)
#pragma unroll
                for (int nt = 0; nt < 4; nt++)
                    mma8(acc[mt][nt], af[mt], bf[nt]);
        }
        __syncthreads();
    }

    // Epilogue: direct float2 stores from C-fragment layout
#pragma unroll
    for (int mt = 0; mt < 4; mt++) {
        const int row = bm + wm + mt * 16 + g;
#pragma unroll
        for (int nt = 0; nt < 4; nt++) {
            const int col = bn + wn + nt * 8 + 2 * tig;
            *(float2*)(C + (size_t)row * N + col) =
                make_float2(acc[mt][nt][0], acc[mt][nt][1]);
            *(float2*)(C + (size_t)(row + 8) * N + col) =
                make_float2(acc[mt][nt][2], acc[mt][nt][3]);
        }
    }
}

// ---------------------------------------------------------------------------
// Flash attention, register-resident softmax/O. Block = (b,h,64 Q rows),
// 128 threads (4 warps x 16 Q rows). K/V cp.async double-buffered.
// ---------------------------------------------------------------------------
static constexpr int KS_LD = 68, VS_LD = 72, PS_LD = 68;  // floats
static constexpr int KS_F = 64 * KS_LD;                   // 4352
static constexpr int VS_F = 64 * VS_LD;                   // 4608
static constexpr int STG_F = KS_F + VS_F;                 // 8960
static constexpr int PS_OFF = 2 * STG_F;                  // 17920
static constexpr int FL_SMEM = (PS_OFF + 64 * PS_LD) * 4; // 89088 bytes

__global__ void __launch_bounds__(128)
flash_attn(const float* __restrict__ qkv, float* __restrict__ y)
{
    extern __shared__ float sm[];
    const uint32_t sb = smem_u32(sm);
    const int tid = threadIdx.x, warp = tid >> 5, lane = tid & 31;
    const int g = lane >> 2, tig = lane & 3;
    const int q0 = blockIdx.x * 64;
    const int b = blockIdx.y >> 4, h = blockIdx.y & 15;
    const float* base = qkv + (size_t)b * Tt * 3 * Cc + (size_t)h * Dd;
    float* Ps = sm + PS_OFF;

    auto load_kv = [&](int kvi, int s) {
        const float* gk = base + Cc + (size_t)(kvi * 64) * (3 * Cc);
        const float* gv = base + 2 * Cc + (size_t)(kvi * 64) * (3 * Cc);
        const uint32_t dk = sb + (uint32_t)s * STG_F * 4;
        const uint32_t dv = dk + KS_F * 4;
#pragma unroll
        for (int it = 0; it < 8; it++) {
            int j = tid + it * 128;            // 1024 chunks (64 rows x 16)
            int r = j >> 4, ch = j & 15;
            cpa16(dk + (uint32_t)(r * KS_LD + ch * 4) * 4,
                  gk + (size_t)r * (3 * Cc) + ch * 4);
        }
#pragma unroll
        for (int it = 0; it < 8; it++) {
            int j = tid + it * 128;
            int r = j >> 4, ch = j & 15;
            cpa16(dv + (uint32_t)(r * VS_LD + ch * 4) * 4,
                  gv + (size_t)r * (3 * Cc) + ch * 4);
        }
        CP_COMMIT();
    };

    // Q -> Ps staging (group 0), KV(0) -> stage 0 (group 1)
    {
        const float* gq = base + (size_t)q0 * (3 * Cc);
#pragma unroll
        for (int it = 0; it < 8; it++) {
            int j = tid + it * 128;
            int r = j >> 4, ch = j & 15;
            cpa16(sb + (uint32_t)(PS_OFF + r * PS_LD + ch * 4) * 4,
                  gq + (size_t)r * (3 * Cc) + ch * 4);
        }
        CP_COMMIT();
    }
    load_kv(0, 0);
    CP_WAIT(1);          // Q arrived
    __syncthreads();

    // Q fragments in registers (pre-scaled by 1/sqrt(D), tf32)
    uint32_t qa[8][4];
#pragma unroll
    for (int kt = 0; kt < 8; kt++) {
        const float* p = Ps + (warp * 16 + g) * PS_LD + kt * 8 + tig;
        qa[kt][0] = f2tf(0.125f * p[0]);
        qa[kt][1] = f2tf(0.125f * p[8 * PS_LD]);
        qa[kt][2] = f2tf(0.125f * p[4]);
        qa[kt][3] = f2tf(0.125f * p[8 * PS_LD + 4]);
    }

    float oacc[8][4];
#pragma unroll
    for (int nt = 0; nt < 8; nt++)
#pragma unroll
        for (int q = 0; q < 4; q++) oacc[nt][q] = 0.0f;
    float m0 = -CUDART_INF_F, m1 = -CUDART_INF_F, l0 = 0.0f, l1 = 0.0f;

#pragma unroll 1
    for (int it = 0; it < Tt / 64; it++) {
        CP_WAIT(0);
        __syncthreads();
        if (it + 1 < Tt / 64) load_kv(it + 1, (it + 1) & 1);
        const float* Ks = sm + (it & 1) * STG_F;
        const float* Vs = Ks + KS_F;

        // S = Q @ K^T (16x64 per warp)
        float sacc[8][4];
#pragma unroll
        for (int nt = 0; nt < 8; nt++)
#pragma unroll
            for (int q = 0; q < 4; q++) sacc[nt][q] = 0.0f;
#pragma unroll
        for (int kt = 0; kt < 8; kt++) {
#pragma unroll
            for (int nt = 0; nt < 8; nt++) {
                const float* p = Ks + (nt * 8 + g) * KS_LD + kt * 8 + tig;
                uint32_t bf[2] = { f2tf(p[0]), f2tf(p[4]) };
                mma8(sacc[nt], qa[kt], bf);
            }
        }

        // Online softmax fully in registers (rows g and g+8)
        float tm0 = -CUDART_INF_F, tm1 = -CUDART_INF_F;
#pragma unroll
        for (int nt = 0; nt < 8; nt++) {
            tm0 = fmaxf(tm0, fmaxf(sacc[nt][0], sacc[nt][1]));
            tm1 = fmaxf(tm1, fmaxf(sacc[nt][2], sacc[nt][3]));
        }
        tm0 = fmaxf(tm0, __shfl_xor_sync(0xffffffffu, tm0, 1));
        tm0 = fmaxf(tm0, __shfl_xor_sync(0xffffffffu, tm0, 2));
        tm1 = fmaxf(tm1, __shfl_xor_sync(0xffffffffu, tm1, 1));
        tm1 = fmaxf(tm1, __shfl_xor_sync(0xffffffffu, tm1, 2));
        const float mn0 = fmaxf(m0, tm0), mn1 = fmaxf(m1, tm1);
        const float f0 = __expf(m0 - mn0), f1 = __expf(m1 - mn1);
        float p0 = 0.0f, p1 = 0.0f;
#pragma unroll
        for (int nt = 0; nt < 8; nt++) {
            float e0 = __expf(sacc[nt][0] - mn0);
            float e1 = __expf(sacc[nt][1] - mn0);
            float e2 = __expf(sacc[nt][2] - mn1);
            float e3 = __expf(sacc[nt][3] - mn1);
            sacc[nt][0] = e0; sacc[nt][1] = e1;
            sacc[nt][2] = e2; sacc[nt][3] = e3;
            p0 += e0 + e1; p1 += e2 + e3;
        }
        p0 += __shfl_xor_sync(0xffffffffu, p0, 1);
        p0 += __shfl_xor_sync(0xffffffffu, p0, 2);
        p1 += __shfl_xor_sync(0xffffffffu, p1, 1);
        p1 += __shfl_xor_sync(0xffffffffu, p1, 2);
        l0 = l0 * f0 + p0; l1 = l1 * f1 + p1;
        m0 = mn0; m1 = mn1;
#pragma unroll
        for (int nt = 0; nt < 8; nt++) {
            oacc[nt][0] *= f0; oacc[nt][1] *= f0;
            oacc[nt][2] *= f1; oacc[nt][3] *= f1;
        }

        // P -> per-warp smem region (tf32 bits), then PV
        __syncwarp();   // prior iteration's P reads complete
        uint32_t* Pu = (uint32_t*)Ps;
        const int pr = warp * 16 + g;
#pragma unroll
        for (int nt = 0; nt < 8; nt++) {
            const int col = nt * 8 + 2 * tig;
            Pu[pr * PS_LD + col]           = f2tf(sacc[nt][0]);
            Pu[pr * PS_LD + col + 1]       = f2tf(sacc[nt][1]);
            Pu[(pr + 8) * PS_LD + col]     = f2tf(sacc[nt][2]);
            Pu[(pr + 8) * PS_LD + col + 1] = f2tf(sacc[nt][3]);
        }
        __syncwarp();

#pragma unroll
        for (int kt = 0; kt < 8; kt++) {
            const uint32_t* pp = Pu + pr * PS_LD + kt * 8 + tig;
            uint32_t pa[4] = { pp[0], pp[8 * PS_LD], pp[4], pp[8 * PS_LD + 4] };
#pragma unroll
            for (int nt = 0; nt < 8; nt++) {
                const float* v = Vs + (kt * 8 + tig) * VS_LD + nt * 8 + g;
                uint32_t bf[2] = { f2tf(v[0]), f2tf(v[4 * VS_LD]) };
                mma8(oacc[nt], pa, bf);
            }
        }
    }

    // Epilogue: O / l -> y
    const float i0 = 1.0f / l0, i1 = 1.0f / l1;
    float* yb = y + (size_t)b * Tt * Cc + (size_t)(q0 + warp * 16 + g) * Cc + h * Dd;
#pragma unroll
    for (int nt = 0; nt < 8; nt++) {
        const int col = nt * 8 + 2 * tig;
        *(float2*)(yb + col) = make_float2(oacc[nt][0] * i0, oacc[nt][1] * i0);
        *(float2*)(yb + 8 * Cc + col) =
            make_float2(oacc[nt][2] * i1, oacc[nt][3] * i1);
    }
}

// ---------------------------------------------------------------------------
extern "C" void kernel_launch(void* const* d_in, const int* in_sizes, int n_in,
                              void* d_out, int out_size)
{
    const float* x     = (const float*)d_in[0];
    const float* W_qkv = (const float*)d_in[3];
    const float* W_out = (const float*)d_in[4];
    float* out = (float*)d_out;

    float *qkv, *y;
    cudaGetSymbolAddress((void**)&qkv, g_qkv);
    cudaGetSymbolAddress((void**)&y, g_y);

    cudaFuncSetAttribute(gemm_nt_mma, cudaFuncAttributeMaxDynamicSharedMemorySize,
                         GSMEM);
    cudaFuncSetAttribute(flash_attn, cudaFuncAttributeMaxDynamicSharedMemorySize,
                         FL_SMEM);

    // 1) qkv = x @ W_qkv^T : [4096, 3072, 1024]
    gemm_nt_mma<<<dim3(3 * Cc / 128, Bb * Tt / 128), 256, GSMEM>>>(
        x, W_qkv, qkv, 3 * Cc, Cc);

    // 2) fused attention -> y [B, T, C]
    flash_attn<<<dim3(Tt / 64, Bb * Hh), 128, FL_SMEM>>>(qkv, y);

    // 3) out = y @ W_out^T : [4096, 1024, 1024]
    gemm_nt_mma<<<dim3(Cc / 128, Bb * Tt / 128), 256, GSMEM>>>(
        y, W_out, out, Cc, Cc);
}

// round 7
// speedup vs baseline: 2.8769x; 1.1760x over previous
#include <cuda_runtime.h>
#include <cstdint>
#include <math_constants.h>

// Problem shape (fixed)
static constexpr int Bb = 2, Tt = 2048, Cc = 1024, Hh = 16, Dd = 64;

// Scratch (allocation-free device globals)
__device__ __align__(256) float g_qkv[(size_t)Bb * Tt * 3 * Cc];   // 50 MB
__device__ __align__(256) float g_y[(size_t)Bb * Tt * Cc];         // 16 MB
__device__ __align__(256) float g_xr[(size_t)Bb * Tt * Cc];        // 16 MB
__device__ __align__(256) float g_wq[(size_t)3 * Cc * Cc];         // 12 MB
__device__ __align__(256) float g_wo[(size_t)Cc * Cc];             // 4 MB

// ---------------------------------------------------------------------------
// Helpers
// ---------------------------------------------------------------------------
__device__ __forceinline__ uint32_t smem_u32(const void* p) {
    uint32_t a;
    asm("{ .reg .u64 t; cvta.to.shared.u64 t, %1; cvt.u32.u64 %0, t; }"
        : "=r"(a) : "l"(p));
    return a;
}
__device__ __forceinline__ uint32_t f2tf(float x) {
    uint32_t r;
    asm("cvt.rna.tf32.f32 %0, %1;" : "=r"(r) : "f"(x));
    return r;
}
__device__ __forceinline__ void mma8(float c[4], const uint32_t a[4],
                                     const uint32_t b[2]) {
    asm volatile(
        "mma.sync.aligned.m16n8k8.row.col.f32.tf32.tf32.f32 "
        "{%0,%1,%2,%3}, {%4,%5,%6,%7}, {%8,%9}, {%0,%1,%2,%3};"
        : "+f"(c[0]), "+f"(c[1]), "+f"(c[2]), "+f"(c[3])
        : "r"(a[0]), "r"(a[1]), "r"(a[2]), "r"(a[3]), "r"(b[0]), "r"(b[1]));
}
__device__ __forceinline__ void cpa16(uint32_t dst, const void* src) {
    asm volatile("cp.async.cg.shared.global [%0], [%1], 16;"
                 :: "r"(dst), "l"(src));
}
#define CP_COMMIT() asm volatile("cp.async.commit_group;" ::: "memory")
#define CP_WAIT(n)  asm volatile("cp.async.wait_group %0;" :: "n"(n) : "memory")
#define LDSM4(R0, R1, R2, R3, ADDR)                                          \
    asm volatile("ldmatrix.sync.aligned.m8n8.x4.shared.b16 {%0,%1,%2,%3}, [%4];" \
                 : "=r"(R0), "=r"(R1), "=r"(R2), "=r"(R3) : "r"(ADDR))

// ---------------------------------------------------------------------------
// Elementwise tf32 pre-round: dst[i] = bits(cvt.rna.tf32(src[i]))
// ---------------------------------------------------------------------------
__global__ void __launch_bounds__(256) round_tf32(const float* __restrict__ src,
                                                  float* __restrict__ dst, int n4)
{
    int i = blockIdx.x * 256 + threadIdx.x;
    if (i < n4) {
        float4 v = ((const float4*)src)[i];
        v.x = __uint_as_float(f2tf(v.x));
        v.y = __uint_as_float(f2tf(v.y));
        v.z = __uint_as_float(f2tf(v.z));
        v.w = __uint_as_float(f2tf(v.w));
        ((float4*)dst)[i] = v;
    }
}

// ---------------------------------------------------------------------------
// Projection GEMM: C[M,N] = A[M,K] @ B[N,K]^T (row-major, K contiguous)
// Inputs pre-rounded to tf32 bits. ldmatrix fragment loads, zero inner cvt.
// 128x128x32 tiles, 256 threads, warp tile 64x32, cp.async double buffer.
// ---------------------------------------------------------------------------
static constexpr int GLD = 36;                 // smem row stride (floats)
static constexpr int GSTG = 2 * 128 * GLD;     // floats per stage (A+B)
static constexpr int GSMEM = 2 * GSTG * 4;     // 73728 bytes

__global__ void __launch_bounds__(256, 2)
gemm_nt_mma(const float* __restrict__ A, const float* __restrict__ B,
            float* __restrict__ C, int N, int K, int round_out)
{
    extern __shared__ float sm[];
    const uint32_t sb = smem_u32(sm);
    const int tid = threadIdx.x, warp = tid >> 5, lane = tid & 31;
    const int g = lane >> 2, tig = lane & 3;
    const int bm = blockIdx.y * 128, bn = blockIdx.x * 128;
    const int wm = (warp >> 2) * 64, wn = (warp & 3) * 32;

    // ldmatrix per-thread fragment offsets (bytes, within a stage)
    const uint32_t a_off =
        ((uint32_t)(wm + (lane & 15)) * GLD + ((lane >> 4) << 2)) * 4;
    const uint32_t b_off = (uint32_t)128 * GLD * 4 +
        ((uint32_t)(wn + ((lane >> 4) << 3) + (lane & 7)) * GLD +
         (((lane >> 3) & 1) << 2)) * 4;

    float acc[4][4][4];
#pragma unroll
    for (int mt = 0; mt < 4; mt++)
#pragma unroll
        for (int nt = 0; nt < 4; nt++)
#pragma unroll
            for (int q = 0; q < 4; q++) acc[mt][nt][q] = 0.0f;

    auto load_stage = [&](int c, int s) {
        const float* ga = A + (size_t)bm * K + c * 32;
        const float* gb = B + (size_t)bn * K + c * 32;
        const uint32_t da = sb + (uint32_t)s * GSTG * 4;
        const uint32_t db = da + 128 * GLD * 4;
#pragma unroll
        for (int it = 0; it < 4; it++) {
            int j = tid + it * 256;
            int r = j >> 3, ch = j & 7;
            cpa16(da + (uint32_t)(r * GLD + ch * 4) * 4,
                  ga + (size_t)r * K + ch * 4);
        }
#pragma unroll
        for (int it = 0; it < 4; it++) {
            int j = tid + it * 256;
            int r = j >> 3, ch = j & 7;
            cpa16(db + (uint32_t)(r * GLD + ch * 4) * 4,
                  gb + (size_t)r * K + ch * 4);
        }
        CP_COMMIT();
    };

    const int NCH = K / 32;
    load_stage(0, 0);
#pragma unroll 1
    for (int c = 0; c < NCH; c++) {
        CP_WAIT(0);
        __syncthreads();
        if (c + 1 < NCH) load_stage(c + 1, (c + 1) & 1);
        const uint32_t stg = sb + (uint32_t)(c & 1) * GSTG * 4;
        const uint32_t aa = stg + a_off;
        const uint32_t ba = stg + b_off;
#pragma unroll
        for (int ks = 0; ks < 4; ks++) {
            const uint32_t kb = (uint32_t)(ks * 8) * 4;
            uint32_t af[4][4], bf[4][2];
#pragma unroll
            for (int mt = 0; mt < 4; mt++)
                LDSM4(af[mt][0], af[mt][1], af[mt][2], af[mt][3],
                      aa + (uint32_t)mt * 16 * GLD * 4 + kb);
#pragma unroll
            for (int j = 0; j < 2; j++)
                LDSM4(bf[2 * j][0], bf[2 * j][1], bf[2 * j + 1][0],
                      bf[2 * j + 1][1], ba + (uint32_t)j * 16 * GLD * 4 + kb);
#pragma unroll
            for (int mt = 0; mt < 4; mt++)
#pragma unroll
                for (int nt = 0; nt < 4; nt++)
                    mma8(acc[mt][nt], af[mt], bf[nt]);
        }
        __syncthreads();
    }

    // Epilogue: direct float2 stores (optionally tf32-rounded for next stage)
#pragma unroll
    for (int mt = 0; mt < 4; mt++) {
        const int row = bm + wm + mt * 16 + g;
#pragma unroll
        for (int nt = 0; nt < 4; nt++) {
            const int col = bn + wn + nt * 8 + 2 * tig;
            float4 v = make_float4(acc[mt][nt][0], acc[mt][nt][1],
                                   acc[mt][nt][2], acc[mt][nt][3]);
            if (round_out) {
                v.x = __uint_as_float(f2tf(v.x));
                v.y = __uint_as_float(f2tf(v.y));
                v.z = __uint_as_float(f2tf(v.z));
                v.w = __uint_as_float(f2tf(v.w));
            }
            *(float2*)(C + (size_t)row * N + col) = make_float2(v.x, v.y);
            *(float2*)(C + (size_t)(row + 8) * N + col) = make_float2(v.z, v.w);
        }
    }
}

// ---------------------------------------------------------------------------
// Flash attention (R4-proven layout): register softmax/O, scalar LDS operand
// loads. qkv is pre-rounded tf32 bits, so no cvt on Q/K/V loads.
// Block = (b,h,64 Q rows), 128 threads. K/V cp.async double-buffered.
// ---------------------------------------------------------------------------
static constexpr int KS_LD = 68, VS_LD = 72, PS_LD = 68;  // floats
static constexpr int KS_F = 64 * KS_LD;                   // 4352
static constexpr int VS_F = 64 * VS_LD;                   // 4608
static constexpr int STG_F = KS_F + VS_F;                 // 8960
static constexpr int PS_OFF = 2 * STG_F;                  // 17920
static constexpr int FL_SMEM = (PS_OFF + 64 * PS_LD) * 4; // 89088 bytes

__global__ void __launch_bounds__(128)
flash_attn(const float* __restrict__ qkv, float* __restrict__ y)
{
    extern __shared__ float sm[];
    const uint32_t sb = smem_u32(sm);
    const int tid = threadIdx.x, warp = tid >> 5, lane = tid & 31;
    const int g = lane >> 2, tig = lane & 3;
    const int q0 = blockIdx.x * 64;
    const int b = blockIdx.y >> 4, h = blockIdx.y & 15;
    const float* base = qkv + (size_t)b * Tt * 3 * Cc + (size_t)h * Dd;
    float* Ps = sm + PS_OFF;

    auto load_kv = [&](int kvi, int s) {
        const float* gk = base + Cc + (size_t)(kvi * 64) * (3 * Cc);
        const float* gv = base + 2 * Cc + (size_t)(kvi * 64) * (3 * Cc);
        const uint32_t dk = sb + (uint32_t)s * STG_F * 4;
        const uint32_t dv = dk + KS_F * 4;
#pragma unroll
        for (int it = 0; it < 8; it++) {
            int j = tid + it * 128;            // 1024 chunks (64 rows x 16)
            int r = j >> 4, ch = j & 15;
            cpa16(dk + (uint32_t)(r * KS_LD + ch * 4) * 4,
                  gk + (size_t)r * (3 * Cc) + ch * 4);
        }
#pragma unroll
        for (int it = 0; it < 8; it++) {
            int j = tid + it * 128;
            int r = j >> 4, ch = j & 15;
            cpa16(dv + (uint32_t)(r * VS_LD + ch * 4) * 4,
                  gv + (size_t)r * (3 * Cc) + ch * 4);
        }
        CP_COMMIT();
    };

    // Q -> Ps staging (group 0), KV(0) -> stage 0 (group 1)
    {
        const float* gq = base + (size_t)q0 * (3 * Cc);
#pragma unroll
        for (int it = 0; it < 8; it++) {
            int j = tid + it * 128;
            int r = j >> 4, ch = j & 15;
            cpa16(sb + (uint32_t)(PS_OFF + r * PS_LD + ch * 4) * 4,
                  gq + (size_t)r * (3 * Cc) + ch * 4);
        }
        CP_COMMIT();
    }
    load_kv(0, 0);
    CP_WAIT(1);          // Q arrived
    __syncthreads();

    // Q fragments in registers; scale by 1/8 (exact on tf32 bits)
    uint32_t qa[8][4];
#pragma unroll
    for (int kt = 0; kt < 8; kt++) {
        const float* p = Ps + (warp * 16 + g) * PS_LD + kt * 8 + tig;
        qa[kt][0] = __float_as_uint(0.125f * p[0]);
        qa[kt][1] = __float_as_uint(0.125f * p[8 * PS_LD]);
        qa[kt][2] = __float_as_uint(0.125f * p[4]);
        qa[kt][3] = __float_as_uint(0.125f * p[8 * PS_LD + 4]);
    }

    float oacc[8][4];
#pragma unroll
    for (int nt = 0; nt < 8; nt++)
#pragma unroll
        for (int q = 0; q < 4; q++) oacc[nt][q] = 0.0f;
    float m0 = -CUDART_INF_F, m1 = -CUDART_INF_F, l0 = 0.0f, l1 = 0.0f;

#pragma unroll 1
    for (int it = 0; it < Tt / 64; it++) {
        CP_WAIT(0);
        __syncthreads();
        if (it + 1 < Tt / 64) load_kv(it + 1, (it + 1) & 1);
        const float* Ks = sm + (it & 1) * STG_F;
        const float* Vs = Ks + KS_F;

        // S = Q @ K^T (16x64 per warp)
        float sacc[8][4];
#pragma unroll
        for (int nt = 0; nt < 8; nt++)
#pragma unroll
            for (int q = 0; q < 4; q++) sacc[nt][q] = 0.0f;
#pragma unroll
        for (int kt = 0; kt < 8; kt++) {
#pragma unroll
            for (int nt = 0; nt < 8; nt++) {
                const float* p = Ks + (nt * 8 + g) * KS_LD + kt * 8 + tig;
                uint32_t bf[2] = { __float_as_uint(p[0]),
                                   __float_as_uint(p[4]) };
                mma8(sacc[nt], qa[kt], bf);
            }
        }

        // Online softmax fully in registers (rows g and g+8)
        float tm0 = -CUDART_INF_F, tm1 = -CUDART_INF_F;
#pragma unroll
        for (int nt = 0; nt < 8; nt++) {
            tm0 = fmaxf(tm0, fmaxf(sacc[nt][0], sacc[nt][1]));
            tm1 = fmaxf(tm1, fmaxf(sacc[nt][2], sacc[nt][3]));
        }
        tm0 = fmaxf(tm0, __shfl_xor_sync(0xffffffffu, tm0, 1));
        tm0 = fmaxf(tm0, __shfl_xor_sync(0xffffffffu, tm0, 2));
        tm1 = fmaxf(tm1, __shfl_xor_sync(0xffffffffu, tm1, 1));
        tm1 = fmaxf(tm1, __shfl_xor_sync(0xffffffffu, tm1, 2));
        const float mn0 = fmaxf(m0, tm0), mn1 = fmaxf(m1, tm1);
        const float f0 = __expf(m0 - mn0), f1 = __expf(m1 - mn1);
        float p0 = 0.0f, p1 = 0.0f;
#pragma unroll
        for (int nt = 0; nt < 8; nt++) {
            float e0 = __expf(sacc[nt][0] - mn0);
            float e1 = __expf(sacc[nt][1] - mn0);
            float e2 = __expf(sacc[nt][2] - mn1);
            float e3 = __expf(sacc[nt][3] - mn1);
            sacc[nt][0] = e0; sacc[nt][1] = e1;
            sacc[nt][2] = e2; sacc[nt][3] = e3;
            p0 += e0 + e1; p1 += e2 + e3;
        }
        p0 += __shfl_xor_sync(0xffffffffu, p0, 1);
        p0 += __shfl_xor_sync(0xffffffffu, p0, 2);
        p1 += __shfl_xor_sync(0xffffffffu, p1, 1);
        p1 += __shfl_xor_sync(0xffffffffu, p1, 2);
        l0 = l0 * f0 + p0; l1 = l1 * f1 + p1;
        m0 = mn0; m1 = mn1;
#pragma unroll
        for (int nt = 0; nt < 8; nt++) {
            oacc[nt][0] *= f0; oacc[nt][1] *= f0;
            oacc[nt][2] *= f1; oacc[nt][3] *= f1;
        }

        // P -> per-warp smem rows (tf32 bits), then PV
        __syncwarp();
        uint32_t* Pu = (uint32_t*)Ps;
        const int pr = warp * 16 + g;
#pragma unroll
        for (int nt = 0; nt < 8; nt++) {
            const int col = nt * 8 + 2 * tig;
            Pu[pr * PS_LD + col]           = f2tf(sacc[nt][0]);
            Pu[pr * PS_LD + col + 1]       = f2tf(sacc[nt][1]);
            Pu[(pr + 8) * PS_LD + col]     = f2tf(sacc[nt][2]);
            Pu[(pr + 8) * PS_LD + col + 1] = f2tf(sacc[nt][3]);
        }
        __syncwarp();

#pragma unroll
        for (int kt = 0; kt < 8; kt++) {
            const uint32_t* pp = Pu + pr * PS_LD + kt * 8 + tig;
            uint32_t pa[4] = { pp[0], pp[8 * PS_LD], pp[4], pp[8 * PS_LD + 4] };
#pragma unroll
            for (int nt = 0; nt < 8; nt++) {
                const float* v = Vs + (kt * 8 + tig) * VS_LD + nt * 8 + g;
                uint32_t bf[2] = { __float_as_uint(v[0]),
                                   __float_as_uint(v[4 * VS_LD]) };
                mma8(oacc[nt], pa, bf);
            }
        }
    }

    // Epilogue: O / l -> y (tf32-rounded for the out-projection)
    const float i0 = 1.0f / l0, i1 = 1.0f / l1;
    float* yb = y + (size_t)b * Tt * Cc + (size_t)(q0 + warp * 16 + g) * Cc + h * Dd;
#pragma unroll
    for (int nt = 0; nt < 8; nt++) {
        const int col = nt * 8 + 2 * tig;
        *(float2*)(yb + col) = make_float2(
            __uint_as_float(f2tf(oacc[nt][0] * i0)),
            __uint_as_float(f2tf(oacc[nt][1] * i0)));
        *(float2*)(yb + 8 * Cc + col) = make_float2(
            __uint_as_float(f2tf(oacc[nt][2] * i1)),
            __uint_as_float(f2tf(oacc[nt][3] * i1)));
    }
}

// ---------------------------------------------------------------------------
extern "C" void kernel_launch(void* const* d_in, const int* in_sizes, int n_in,
                              void* d_out, int out_size)
{
    const float* x     = (const float*)d_in[0];
    const float* W_qkv = (const float*)d_in[3];
    const float* W_out = (const float*)d_in[4];
    float* out = (float*)d_out;

    float *qkv, *y, *xr, *wq, *wo;
    cudaGetSymbolAddress((void**)&qkv, g_qkv);
    cudaGetSymbolAddress((void**)&y, g_y);
    cudaGetSymbolAddress((void**)&xr, g_xr);
    cudaGetSymbolAddress((void**)&wq, g_wq);
    cudaGetSymbolAddress((void**)&wo, g_wo);

    cudaFuncSetAttribute(gemm_nt_mma, cudaFuncAttributeMaxDynamicSharedMemorySize,
                         GSMEM);
    cudaFuncSetAttribute(flash_attn, cudaFuncAttributeMaxDynamicSharedMemorySize,
                         FL_SMEM);

    // 0) pre-round inputs to tf32 bits
    {
        int n4x = Bb * Tt * Cc / 4, n4q = 3 * Cc * Cc / 4, n4o = Cc * Cc / 4;
        round_tf32<<<(n4x + 255) / 256, 256>>>(x, xr, n4x);
        round_tf32<<<(n4q + 255) / 256, 256>>>(W_qkv, wq, n4q);
        round_tf32<<<(n4o + 255) / 256, 256>>>(W_out, wo, n4o);
    }

    // 1) qkv = x @ W_qkv^T : [4096, 3072, 1024], output tf32-rounded
    gemm_nt_mma<<<dim3(3 * Cc / 128, Bb * Tt / 128), 256, GSMEM>>>(
        xr, wq, qkv, 3 * Cc, Cc, 1);

    // 2) fused attention -> y [B, T, C] (tf32-rounded)
    flash_attn<<<dim3(Tt / 64, Bb * Hh), 128, FL_SMEM>>>(qkv, y);

    // 3) out = y @ W_out^T : [4096, 1024, 1024], raw f32 output
    gemm_nt_mma<<<dim3(Cc / 128, Bb * Tt / 128), 256, GSMEM>>>(
        y, wo, out, Cc, Cc, 0);
}

// round 8
// speedup vs baseline: 2.9143x; 1.0130x over previous
#include <cuda_runtime.h>
#include <cstdint>
#include <math_constants.h>

// Problem shape (fixed)
static constexpr int Bb = 2, Tt = 2048, Cc = 1024, Hh = 16, Dd = 64;

// Scratch (allocation-free device globals)
__device__ __align__(256) float g_qkv[(size_t)Bb * Tt * 3 * Cc];   // 50 MB
__device__ __align__(256) float g_y[(size_t)Bb * Tt * Cc];         // 16 MB
__device__ __align__(256) float g_xr[(size_t)Bb * Tt * Cc];        // 16 MB
__device__ __align__(256) float g_wq[(size_t)3 * Cc * Cc];         // 12 MB
__device__ __align__(256) float g_wo[(size_t)Cc * Cc];             // 4 MB

// ---------------------------------------------------------------------------
// Helpers
// ---------------------------------------------------------------------------
__device__ __forceinline__ uint32_t smem_u32(const void* p) {
    uint32_t a;
    asm("{ .reg .u64 t; cvta.to.shared.u64 t, %1; cvt.u32.u64 %0, t; }"
        : "=r"(a) : "l"(p));
    return a;
}
__device__ __forceinline__ uint32_t f2tf(float x) {
    uint32_t r;
    asm("cvt.rna.tf32.f32 %0, %1;" : "=r"(r) : "f"(x));
    return r;
}
__device__ __forceinline__ void mma8(float c[4], const uint32_t a[4],
                                     const uint32_t b[2]) {
    asm volatile(
        "mma.sync.aligned.m16n8k8.row.col.f32.tf32.tf32.f32 "
        "{%0,%1,%2,%3}, {%4,%5,%6,%7}, {%8,%9}, {%0,%1,%2,%3};"
        : "+f"(c[0]), "+f"(c[1]), "+f"(c[2]), "+f"(c[3])
        : "r"(a[0]), "r"(a[1]), "r"(a[2]), "r"(a[3]), "r"(b[0]), "r"(b[1]));
}
__device__ __forceinline__ void cpa16(uint32_t dst, const void* src) {
    asm volatile("cp.async.cg.shared.global [%0], [%1], 16;"
                 :: "r"(dst), "l"(src));
}
#define CP_COMMIT() asm volatile("cp.async.commit_group;" ::: "memory")
#define CP_WAIT(n)  asm volatile("cp.async.wait_group %0;" :: "n"(n) : "memory")
#define LDSM4(R0, R1, R2, R3, ADDR)                                          \
    asm volatile("ldmatrix.sync.aligned.m8n8.x4.shared.b16 {%0,%1,%2,%3}, [%4];" \
                 : "=r"(R0), "=r"(R1), "=r"(R2), "=r"(R3) : "r"(ADDR))

// ---------------------------------------------------------------------------
// Elementwise tf32 pre-round: dst[i] = bits(cvt.rna.tf32(src[i]))
// ---------------------------------------------------------------------------
__global__ void __launch_bounds__(256) round_tf32(const float* __restrict__ src,
                                                  float* __restrict__ dst, int n4)
{
    int i = blockIdx.x * 256 + threadIdx.x;
    if (i < n4) {
        float4 v = ((const float4*)src)[i];
        v.x = __uint_as_float(f2tf(v.x));
        v.y = __uint_as_float(f2tf(v.y));
        v.z = __uint_as_float(f2tf(v.z));
        v.w = __uint_as_float(f2tf(v.w));
        ((float4*)dst)[i] = v;
    }
}

// ---------------------------------------------------------------------------
// Projection GEMM: C[M,N] = A[M,K] @ B[N,K]^T (row-major, K contiguous)
// Inputs pre-rounded to tf32 bits. ldmatrix fragment loads, zero inner cvt.
// 128x128x32 tiles, 256 threads, warp tile 64x32, 3-stage cp.async pipeline.
// ---------------------------------------------------------------------------
static constexpr int GLD = 36;                  // smem row stride (floats)
static constexpr int GSTG_F = 2 * 128 * GLD;    // floats per stage (A+B)
static constexpr int GSMEM = 3 * GSTG_F * 4;    // 110592 bytes

__global__ void __launch_bounds__(256, 2)
gemm_nt_mma(const float* __restrict__ A, const float* __restrict__ B,
            float* __restrict__ C, int N, int K, int round_out)
{
    extern __shared__ float sm[];
    const uint32_t sb = smem_u32(sm);
    const int tid = threadIdx.x, warp = tid >> 5, lane = tid & 31;
    const int g = lane >> 2, tig = lane & 3;
    const int bm = blockIdx.y * 128, bn = blockIdx.x * 128;
    const int wm = (warp >> 2) * 64, wn = (warp & 3) * 32;

    // ldmatrix per-thread fragment offsets (bytes, within a stage)
    const uint32_t a_off =
        ((uint32_t)(wm + (lane & 15)) * GLD + ((lane >> 4) << 2)) * 4;
    const uint32_t b_off = (uint32_t)128 * GLD * 4 +
        ((uint32_t)(wn + ((lane >> 4) << 3) + (lane & 7)) * GLD +
         (((lane >> 3) & 1) << 2)) * 4;

    float acc[4][4][4];
#pragma unroll
    for (int mt = 0; mt < 4; mt++)
#pragma unroll
        for (int nt = 0; nt < 4; nt++)
#pragma unroll
            for (int q = 0; q < 4; q++) acc[mt][nt][q] = 0.0f;

    auto load_stage = [&](int c, int s) {
        const float* ga = A + (size_t)bm * K + c * 32;
        const float* gb = B + (size_t)bn * K + c * 32;
        const uint32_t da = sb + (uint32_t)s * GSTG_F * 4;
        const uint32_t db = da + 128 * GLD * 4;
#pragma unroll
        for (int it = 0; it < 4; it++) {
            int j = tid + it * 256;
            int r = j >> 3, ch = j & 7;
            cpa16(da + (uint32_t)(r * GLD + ch * 4) * 4,
                  ga + (size_t)r * K + ch * 4);
        }
#pragma unroll
        for (int it = 0; it < 4; it++) {
            int j = tid + it * 256;
            int r = j >> 3, ch = j & 7;
            cpa16(db + (uint32_t)(r * GLD + ch * 4) * 4,
                  gb + (size_t)r * K + ch * 4);
        }
        CP_COMMIT();
    };

    const int NCH = K / 32;
    load_stage(0, 0);
    load_stage(1, 1);
#pragma unroll 1
    for (int c = 0; c < NCH; c++) {
        if (c + 2 < NCH) { CP_WAIT(1); } else { CP_WAIT(0); }
        __syncthreads();
        if (c + 2 < NCH) load_stage(c + 2, (c + 2) % 3);
        const uint32_t stg = sb + (uint32_t)(c % 3) * GSTG_F * 4;
        const uint32_t aa = stg + a_off;
        const uint32_t ba = stg + b_off;
#pragma unroll
        for (int ks = 0; ks < 4; ks++) {
            const uint32_t kb = (uint32_t)(ks * 8) * 4;
            uint32_t af[4][4], bf[4][2];
#pragma unroll
            for (int mt = 0; mt < 4; mt++)
                LDSM4(af[mt][0], af[mt][1], af[mt][2], af[mt][3],
                      aa + (uint32_t)mt * 16 * GLD * 4 + kb);
#pragma unroll
            for (int j = 0; j < 2; j++)
                LDSM4(bf[2 * j][0], bf[2 * j][1], bf[2 * j + 1][0],
                      bf[2 * j + 1][1], ba + (uint32_t)j * 16 * GLD * 4 + kb);
#pragma unroll
            for (int mt = 0; mt < 4; mt++)
#pragma unroll
                for (int nt = 0; nt < 4; nt++)
                    mma8(acc[mt][nt], af[mt], bf[nt]);
        }
    }

    // Epilogue: direct float2 stores (optionally tf32-rounded for next stage)
#pragma unroll
    for (int mt = 0; mt < 4; mt++) {
        const int row = bm + wm + mt * 16 + g;
#pragma unroll
        for (int nt = 0; nt < 4; nt++) {
            const int col = bn + wn + nt * 8 + 2 * tig;
            float4 v = make_float4(acc[mt][nt][0], acc[mt][nt][1],
                                   acc[mt][nt][2], acc[mt][nt][3]);
            if (round_out) {
                v.x = __uint_as_float(f2tf(v.x));
                v.y = __uint_as_float(f2tf(v.y));
                v.z = __uint_as_float(f2tf(v.z));
                v.w = __uint_as_float(f2tf(v.w));
            }
            *(float2*)(C + (size_t)row * N + col) = make_float2(v.x, v.y);
            *(float2*)(C + (size_t)(row + 8) * N + col) = make_float2(v.z, v.w);
        }
    }
}

// ---------------------------------------------------------------------------
// Flash attention: register softmax/O. K and P operands via ldmatrix (GEMM's
// proven B/A conventions); V stays scalar [t][d]. qkv pre-rounded tf32 bits.
// Block = (b,h,64 Q rows), 128 threads. K/V cp.async double-buffered.
// ---------------------------------------------------------------------------
static constexpr int KS_LD = 68, VS_LD = 72, PS_LD = 68;  // floats
static constexpr int KS_F = 64 * KS_LD;                   // 4352
static constexpr int VS_F = 64 * VS_LD;                   // 4608
static constexpr int STG_F = KS_F + VS_F;                 // 8960
static constexpr int PS_OFF = 2 * STG_F;                  // 17920
static constexpr int FL_SMEM = (PS_OFF + 64 * PS_LD) * 4; // 89088 bytes

__global__ void __launch_bounds__(128)
flash_attn(const float* __restrict__ qkv, float* __restrict__ y)
{
    extern __shared__ float sm[];
    const uint32_t sb = smem_u32(sm);
    const int tid = threadIdx.x, warp = tid >> 5, lane = tid & 31;
    const int g = lane >> 2, tig = lane & 3;
    const int q0 = blockIdx.x * 64;
    const int b = blockIdx.y >> 4, h = blockIdx.y & 15;
    const float* base = qkv + (size_t)b * Tt * 3 * Cc + (size_t)h * Dd;
    float* Ps = sm + PS_OFF;

    // ldmatrix offsets (bytes): K uses GEMM's B convention, P uses A convention
    const uint32_t k_off =
        ((uint32_t)(((lane >> 4) << 3) + (lane & 7)) * KS_LD +
         (((lane >> 3) & 1) << 2)) * 4;
    const uint32_t p_off =
        ((uint32_t)(warp * 16 + (lane & 15)) * PS_LD + ((lane >> 4) << 2)) * 4;

    auto load_kv = [&](int kvi, int s) {
        const float* gk = base + Cc + (size_t)(kvi * 64) * (3 * Cc);
        const float* gv = base + 2 * Cc + (size_t)(kvi * 64) * (3 * Cc);
        const uint32_t dk = sb + (uint32_t)s * STG_F * 4;
        const uint32_t dv = dk + KS_F * 4;
#pragma unroll
        for (int it = 0; it < 8; it++) {
            int j = tid + it * 128;            // 1024 chunks (64 rows x 16)
            int r = j >> 4, ch = j & 15;
            cpa16(dk + (uint32_t)(r * KS_LD + ch * 4) * 4,
                  gk + (size_t)r * (3 * Cc) + ch * 4);
        }
#pragma unroll
        for (int it = 0; it < 8; it++) {
            int j = tid + it * 128;
            int r = j >> 4, ch = j & 15;
            cpa16(dv + (uint32_t)(r * VS_LD + ch * 4) * 4,
                  gv + (size_t)r * (3 * Cc) + ch * 4);
        }
        CP_COMMIT();
    };

    // Q -> Ps staging (group 0), KV(0) -> stage 0 (group 1)
    {
        const float* gq = base + (size_t)q0 * (3 * Cc);
#pragma unroll
        for (int it = 0; it < 8; it++) {
            int j = tid + it * 128;
            int r = j >> 4, ch = j & 15;
            cpa16(sb + (uint32_t)(PS_OFF + r * PS_LD + ch * 4) * 4,
                  gq + (size_t)r * (3 * Cc) + ch * 4);
        }
        CP_COMMIT();
    }
    load_kv(0, 0);
    CP_WAIT(1);          // Q arrived
    __syncthreads();

    // Q fragments in registers; scale by 1/8 (exact on tf32 bits)
    uint32_t qa[8][4];
#pragma unroll
    for (int kt = 0; kt < 8; kt++) {
        const float* p = Ps + (warp * 16 + g) * PS_LD + kt * 8 + tig;
        qa[kt][0] = __float_as_uint(0.125f * p[0]);
        qa[kt][1] = __float_as_uint(0.125f * p[8 * PS_LD]);
        qa[kt][2] = __float_as_uint(0.125f * p[4]);
        qa[kt][3] = __float_as_uint(0.125f * p[8 * PS_LD + 4]);
    }

    float oacc[8][4];
#pragma unroll
    for (int nt = 0; nt < 8; nt++)
#pragma unroll
        for (int q = 0; q < 4; q++) oacc[nt][q] = 0.0f;
    float m0 = -CUDART_INF_F, m1 = -CUDART_INF_F, l0 = 0.0f, l1 = 0.0f;

#pragma unroll 1
    for (int it = 0; it < Tt / 64; it++) {
        CP_WAIT(0);
        __syncthreads();
        if (it + 1 < Tt / 64) load_kv(it + 1, (it + 1) & 1);
        const uint32_t ks_base = sb + (uint32_t)(it & 1) * STG_F * 4;
        const float* Vs = sm + (it & 1) * STG_F + KS_F;

        // S = Q @ K^T (16x64 per warp), K fragments via ldmatrix
        float sacc[8][4];
#pragma unroll
        for (int nt = 0; nt < 8; nt++)
#pragma unroll
            for (int q = 0; q < 4; q++) sacc[nt][q] = 0.0f;
#pragma unroll
        for (int kt = 0; kt < 8; kt++) {
            const uint32_t kb = (uint32_t)(kt * 8) * 4;
#pragma unroll
            for (int j = 0; j < 4; j++) {
                uint32_t bf[4];
                LDSM4(bf[0], bf[1], bf[2], bf[3],
                      ks_base + k_off + (uint32_t)j * 16 * KS_LD * 4 + kb);
                mma8(sacc[2 * j], qa[kt], bf);
                mma8(sacc[2 * j + 1], qa[kt], bf + 2);
            }
        }

        // Online softmax fully in registers (rows g and g+8)
        float tm0 = -CUDART_INF_F, tm1 = -CUDART_INF_F;
#pragma unroll
        for (int nt = 0; nt < 8; nt++) {
            tm0 = fmaxf(tm0, fmaxf(sacc[nt][0], sacc[nt][1]));
            tm1 = fmaxf(tm1, fmaxf(sacc[nt][2], sacc[nt][3]));
        }
        tm0 = fmaxf(tm0, __shfl_xor_sync(0xffffffffu, tm0, 1));
        tm0 = fmaxf(tm0, __shfl_xor_sync(0xffffffffu, tm0, 2));
        tm1 = fmaxf(tm1, __shfl_xor_sync(0xffffffffu, tm1, 1));
        tm1 = fmaxf(tm1, __shfl_xor_sync(0xffffffffu, tm1, 2));
        const float mn0 = fmaxf(m0, tm0), mn1 = fmaxf(m1, tm1);
        const float f0 = __expf(m0 - mn0), f1 = __expf(m1 - mn1);
        float p0 = 0.0f, p1 = 0.0f;
#pragma unroll
        for (int nt = 0; nt < 8; nt++) {
            float e0 = __expf(sacc[nt][0] - mn0);
            float e1 = __expf(sacc[nt][1] - mn0);
            float e2 = __expf(sacc[nt][2] - mn1);
            float e3 = __expf(sacc[nt][3] - mn1);
            sacc[nt][0] = e0; sacc[nt][1] = e1;
            sacc[nt][2] = e2; sacc[nt][3] = e3;
            p0 += e0 + e1; p1 += e2 + e3;
        }
        p0 += __shfl_xor_sync(0xffffffffu, p0, 1);
        p0 += __shfl_xor_sync(0xffffffffu, p0, 2);
        p1 += __shfl_xor_sync(0xffffffffu, p1, 1);
        p1 += __shfl_xor_sync(0xffffffffu, p1, 2);
        l0 = l0 * f0 + p0; l1 = l1 * f1 + p1;
        m0 = mn0; m1 = mn1;
#pragma unroll
        for (int nt = 0; nt < 8; nt++) {
            oacc[nt][0] *= f0; oacc[nt][1] *= f0;
            oacc[nt][2] *= f1; oacc[nt][3] *= f1;
        }

        // P -> per-warp smem rows (tf32 bits), then PV (P via ldmatrix)
        __syncwarp();
        uint32_t* Pu = (uint32_t*)Ps;
        const int pr = warp * 16 + g;
#pragma unroll
        for (int nt = 0; nt < 8; nt++) {
            const int col = nt * 8 + 2 * tig;
            Pu[pr * PS_LD + col]           = f2tf(sacc[nt][0]);
            Pu[pr * PS_LD + col + 1]       = f2tf(sacc[nt][1]);
            Pu[(pr + 8) * PS_LD + col]     = f2tf(sacc[nt][2]);
            Pu[(pr + 8) * PS_LD + col + 1] = f2tf(sacc[nt][3]);
        }
        __syncwarp();

#pragma unroll
        for (int kt = 0; kt < 8; kt++) {
            uint32_t pa[4];
            LDSM4(pa[0], pa[1], pa[2], pa[3],
                  sb + (uint32_t)PS_OFF * 4 + p_off + (uint32_t)(kt * 8) * 4);
#pragma unroll
            for (int nt = 0; nt < 8; nt++) {
                const float* v = Vs + (kt * 8 + tig) * VS_LD + nt * 8 + g;
                uint32_t bf[2] = { __float_as_uint(v[0]),
                                   __float_as_uint(v[4 * VS_LD]) };
                mma8(oacc[nt], pa, bf);
            }
        }
    }

    // Epilogue: O / l -> y (tf32-rounded for the out-projection)
    const float i0 = 1.0f / l0, i1 = 1.0f / l1;
    float* yb = y + (size_t)b * Tt * Cc + (size_t)(q0 + warp * 16 + g) * Cc + h * Dd;
#pragma unroll
    for (int nt = 0; nt < 8; nt++) {
        const int col = nt * 8 + 2 * tig;
        *(float2*)(yb + col) = make_float2(
            __uint_as_float(f2tf(oacc[nt][0] * i0)),
            __uint_as_float(f2tf(oacc[nt][1] * i0)));
        *(float2*)(yb + 8 * Cc + col) = make_float2(
            __uint_as_float(f2tf(oacc[nt][2] * i1)),
            __uint_as_float(f2tf(oacc[nt][3] * i1)));
    }
}

// ---------------------------------------------------------------------------
extern "C" void kernel_launch(void* const* d_in, const int* in_sizes, int n_in,
                              void* d_out, int out_size)
{
    const float* x     = (const float*)d_in[0];
    const float* W_qkv = (const float*)d_in[3];
    const float* W_out = (const float*)d_in[4];
    float* out = (float*)d_out;

    float *qkv, *y, *xr, *wq, *wo;
    cudaGetSymbolAddress((void**)&qkv, g_qkv);
    cudaGetSymbolAddress((void**)&y, g_y);
    cudaGetSymbolAddress((void**)&xr, g_xr);
    cudaGetSymbolAddress((void**)&wq, g_wq);
    cudaGetSymbolAddress((void**)&wo, g_wo);

    cudaFuncSetAttribute(gemm_nt_mma, cudaFuncAttributeMaxDynamicSharedMemorySize,
                         GSMEM);
    cudaFuncSetAttribute(flash_attn, cudaFuncAttributeMaxDynamicSharedMemorySize,
                         FL_SMEM);

    // 0) pre-round inputs to tf32 bits
    {
        int n4x = Bb * Tt * Cc / 4, n4q = 3 * Cc * Cc / 4, n4o = Cc * Cc / 4;
        round_tf32<<<(n4x + 255) / 256, 256>>>(x, xr, n4x);
        round_tf32<<<(n4q + 255) / 256, 256>>>(W_qkv, wq, n4q);
        round_tf32<<<(n4o + 255) / 256, 256>>>(W_out, wo, n4o);
    }

    // 1) qkv = x @ W_qkv^T : [4096, 3072, 1024], output tf32-rounded
    gemm_nt_mma<<<dim3(3 * Cc / 128, Bb * Tt / 128), 256, GSMEM>>>(
        xr, wq, qkv, 3 * Cc, Cc, 1);

    // 2) fused attention -> y [B, T, C] (tf32-rounded)
    flash_attn<<<dim3(Tt / 64, Bb * Hh), 128, FL_SMEM>>>(qkv, y);

    // 3) out = y @ W_out^T : [4096, 1024, 1024], raw f32 output
    gemm_nt_mma<<<dim3(Cc / 128, Bb * Tt / 128), 256, GSMEM>>>(
        y, wo, out, Cc, Cc, 0);
}